// round 4
// baseline (speedup 1.0000x reference)
#include <cuda_runtime.h>
#include <cuda_bf16.h>
#include <cstdint>

// Problem constants: B=4096, H=1, E=8, IN=256, OUT=256
#define BATCH 4096
#define NEXP  8
#define NIN   256
#define NOUT  256
#define NPAT  256           // 2^E gate patterns
#define NW    8             // 256 bits / 32 = 8 words per i-dimension

// Sign-bit matrices for every gate pattern: Wbits[p][o][iw], bit l of word iw
// corresponds to input index i = iw*32 + l. 2 MB (L2-resident).
__device__ uint32_t g_Wbits[NPAT * NOUT * NW];

// Packed per-sample data produced by kernel1's tail warps.
__device__ __align__(16) uint32_t g_xbits[BATCH * NW];  // sign bits of x
__device__ uint32_t g_pat[BATCH];                       // gate pattern per sample

// ---------------------------------------------------------------------------
// Kernel 1 (fused):
//  Warps [0, 8192):   precompute sign bits of subset sums of expert weights.
//                     Each warp owns (o, iw, q): q selects 4 of the 16 low-
//                     nibble values -> 64 of the 256 patterns. The two-level
//                     DP reproduces EXACT left-to-right ascending-e FP
//                     summation, matching sum_e gate_e * W_e in e order.
//  Warps [8192,12288): per-sample pack: gate pattern + x sign bits.
// ---------------------------------------------------------------------------
__global__ void fused_prep_kernel(
    const float* __restrict__ weight,   // [E, IN, OUT]
    const float* __restrict__ x,        // [B, IN]
    const float* __restrict__ proj_w,   // [E, IN]
    const float* __restrict__ proj_b)   // [E]
{
    const int gw   = (blockIdx.x * blockDim.x + threadIdx.x) >> 5;
    const int lane = threadIdx.x & 31;

    if (gw < 8192) {
        // ----- precompute: o in [0,256), iw in [0,8), q in [0,4) -----
        const int o   = gw >> 5;
        const int rem = gw & 31;
        const int iw  = rem >> 2;
        const int q   = rem & 3;
        const int i   = iw * 32 + lane;

        float w[NEXP];
#pragma unroll
        for (int e = 0; e < NEXP; e++)
            w[e] = __ldg(&weight[(e * NIN + i) * NOUT + o]);

        // Low-nibble DP: sl[pl] = LTR sum of w[0..3] selected by bits of pl.
        float sl[16];
        sl[0] = 0.0f;
#pragma unroll
        for (int e = 0; e < 4; e++) {
#pragma unroll
            for (int m = 0; m < 16; m++) {
                if (m < (1 << e)) sl[m | (1 << e)] = sl[m] + w[e];
            }
        }

        uint32_t keep[2] = {0u, 0u};

#pragma unroll
        for (int t = 0; t < 4; t++) {
            const int pl = q * 4 + t;
            // High-nibble DP seeded with the low partial sum (preserves LTR).
            float sh[16];
            sh[0] = sl[pl];
#pragma unroll
            for (int e = 0; e < 4; e++) {
#pragma unroll
                for (int m = 0; m < 16; m++) {
                    if (m < (1 << e)) sh[m | (1 << e)] = sh[m] + w[4 + e];
                }
            }
#pragma unroll
            for (int ph = 0; ph < 16; ph++) {
                const int idx = ph * 4 + t;   // 0..63 within this warp's set
                uint32_t bal = __ballot_sync(0xffffffffu, sh[ph] > 0.0f);
                if (lane == (idx & 31)) keep[idx >> 5] = bal;
            }
        }

        // Store: 2 words per lane, scattered (inherent to [p][o][iw] layout).
#pragma unroll
        for (int g = 0; g < 2; g++) {
            const int idx = g * 32 + lane;
            const int ph  = idx >> 2;
            const int t   = idx & 3;
            const int p   = ph * 16 + q * 4 + t;
            g_Wbits[(p * NOUT + o) * NW + iw] = keep[g];
        }
    } else {
        // ----- pack: one warp per sample -----
        const int b = gw - 8192;
        if (b >= BATCH) return;
        const float* xb = x + b * NIN;

        float xi[NW];
#pragma unroll
        for (int j = 0; j < NW; j++) xi[j] = __ldg(&xb[j * 32 + lane]);

        uint32_t xbits[NW];
#pragma unroll
        for (int j = 0; j < NW; j++)
            xbits[j] = __ballot_sync(0xffffffffu, xi[j] > 0.0f);

        unsigned p = 0u;
#pragma unroll
        for (int e = 0; e < NEXP; e++) {
            float s = 0.0f;
#pragma unroll
            for (int j = 0; j < NW; j++)
                s += xi[j] * __ldg(&proj_w[e * NIN + j * 32 + lane]);
#pragma unroll
            for (int d = 16; d > 0; d >>= 1)
                s += __shfl_xor_sync(0xffffffffu, s, d);
            if (s + __ldg(&proj_b[e]) > 0.0f) p |= (1u << e);
        }

        if (lane == 0) {
            uint4* dst = reinterpret_cast<uint4*>(&g_xbits[b * NW]);
            dst[0] = make_uint4(xbits[0], xbits[1], xbits[2], xbits[3]);
            dst[1] = make_uint4(xbits[4], xbits[5], xbits[6], xbits[7]);
            g_pat[b] = p;
        }
    }
}

// ---------------------------------------------------------------------------
// Kernel 2: pure XNOR-popcount streaming. 2 warps per sample; per output,
// each lane loads 2 CONSECUTIVE uint4 (32B contiguous) so every LDG.128
// touches only 8 cache lines across the warp. 8 independent LDGs in flight.
//  y[b,o] = (256 - 2*popc(xbits ^ Wbits[p][o])) * scale[o];  p==0 -> 0.
// ---------------------------------------------------------------------------
__global__ void __launch_bounds__(256, 2) binlinear_kernel(
    const float* __restrict__ scale,    // [OUT]
    float* __restrict__ out)            // [B, OUT]
{
    const int gw   = (blockIdx.x * blockDim.x + threadIdx.x) >> 5;
    const int lane = threadIdx.x & 31;
    const int b    = gw >> 1;
    const int half = gw & 1;

    const uint32_t p = __ldg(&g_pat[b]);
    float* outb = out + b * NOUT + half * 128;

    if (p == 0u) {   // w == 0 -> sign 0 -> y == 0 (warp-uniform)
#pragma unroll
        for (int j = 0; j < 4; j++) outb[j * 32 + lane] = 0.0f;
        return;
    }

    const uint4* xp = reinterpret_cast<const uint4*>(&g_xbits[b * NW]);
    const uint4 xa = __ldg(xp);
    const uint4 xc = __ldg(xp + 1);

    const uint4* wrow = reinterpret_cast<const uint4*>(g_Wbits) + p * (NOUT * NW / 4);

#pragma unroll
    for (int j = 0; j < 4; j++) {
        const int o = half * 128 + j * 32 + lane;
        uint4 a = __ldg(&wrow[o * 2 + 0]);
        uint4 c = __ldg(&wrow[o * 2 + 1]);
        int acc = __popc(xa.x ^ a.x) + __popc(xa.y ^ a.y)
                + __popc(xa.z ^ a.z) + __popc(xa.w ^ a.w)
                + __popc(xc.x ^ c.x) + __popc(xc.y ^ c.y)
                + __popc(xc.z ^ c.z) + __popc(xc.w ^ c.w);
        outb[j * 32 + lane] = (float)(NIN - 2 * acc) * __ldg(&scale[o]);
    }
}

// ---------------------------------------------------------------------------
// Launch. Inputs identified defensively by element count (all distinct).
// ---------------------------------------------------------------------------
extern "C" void kernel_launch(void* const* d_in, const int* in_sizes, int n_in,
                              void* d_out, int out_size)
{
    const float* x      = nullptr;
    const float* weight = nullptr;
    const float* proj_w = nullptr;
    const float* proj_b = nullptr;
    const float* scale  = nullptr;

    for (int k = 0; k < n_in; k++) {
        switch (in_sizes[k]) {
            case BATCH * NIN:        x      = (const float*)d_in[k]; break; // 1048576
            case NEXP * NIN * NOUT:  weight = (const float*)d_in[k]; break; // 524288
            case NEXP * NIN:         proj_w = (const float*)d_in[k]; break; // 2048
            case NEXP:               proj_b = (const float*)d_in[k]; break; // 8
            case NOUT:               scale  = (const float*)d_in[k]; break; // 256
            default: break;
        }
    }

    float* out = (float*)d_out;

    // 12288 warps: 8192 precompute + 4096 pack. 1536 blocks x 256 threads.
    fused_prep_kernel<<<1536, 256>>>(weight, x, proj_w, proj_b);
    // 8192 warps: 2 per sample. 1024 blocks x 256 threads.
    binlinear_kernel<<<1024, 256>>>(scale, out);
}